// round 4
// baseline (speedup 1.0000x reference)
#include <cuda_runtime.h>
#include <cuda_fp16.h>
#include <cstdint>

// ---------------- problem constants ----------------
static constexpr int BATCH = 4096;
static constexpr int IN_SZ = 1024;
static constexpr int HID   = 2048;
static constexpr int KDIM  = 3072;   // IN_SZ + HID
static constexpr int NDIM  = 8192;   // 4*HID, gate-interleaved rows: n = 4*h + gate

// ---------------- GEMM tiling ----------------
static constexpr int BM = 128;
static constexpr int BN = 128;
static constexpr int BK = 64;
static constexpr int KITERS = KDIM / BK;     // 48
static constexpr int STAGES = 3;
static constexpr int A_TILE = BM * BK * 2;   // 16 KB
static constexpr int B_TILE = BN * BK * 2;   // 16 KB
static constexpr int STAGE_BYTES = A_TILE + B_TILE;   // 32 KB
static constexpr int SMEM_CTRL = 1024;
static constexpr int SMEM_TOTAL = SMEM_CTRL + STAGES * STAGE_BYTES;  // 99328

// ---------------- device scratch (no allocs allowed) ----------------
__device__ __half g_A[(size_t)BATCH * KDIM];   // fp16 [x_t | h_prev], 25 MB
__device__ __half g_W[(size_t)NDIM * KDIM];    // fp16 gate-interleaved, 50 MB
__device__ float  g_bias[NDIM];

// ---------------- helpers ----------------
__device__ __forceinline__ uint32_t smem_u32(const void* p) {
    uint32_t a;
    asm("{ .reg .u64 t; cvta.to.shared.u64 t, %1; cvt.u32.u64 %0, t; }" : "=r"(a) : "l"(p));
    return a;
}
__device__ __forceinline__ uint32_t swz128(uint32_t off) {
    return off ^ ((off >> 3) & 0x70);
}
__device__ __forceinline__ void cp_async16(uint32_t dst, const void* src) {
    asm volatile("cp.async.cg.shared.global [%0], [%1], 16;" :: "r"(dst), "l"(src) : "memory");
}
__device__ __forceinline__ void cp_commit() {
    asm volatile("cp.async.commit_group;" ::: "memory");
}
template <int N>
__device__ __forceinline__ void cp_wait() {
    asm volatile("cp.async.wait_group %0;" :: "n"(N) : "memory");
}
__device__ __forceinline__ void ldsm4(uint32_t* r, uint32_t addr) {
    asm volatile("ldmatrix.sync.aligned.m8n8.x4.shared.b16 {%0,%1,%2,%3}, [%4];"
                 : "=r"(r[0]), "=r"(r[1]), "=r"(r[2]), "=r"(r[3]) : "r"(addr));
}
__device__ __forceinline__ void mma16816(float* c, const uint32_t* a, uint32_t b0, uint32_t b1) {
    asm volatile("mma.sync.aligned.m16n8k16.row.col.f32.f16.f16.f32 "
                 "{%0,%1,%2,%3}, {%4,%5,%6,%7}, {%8,%9}, {%0,%1,%2,%3};"
                 : "+f"(c[0]), "+f"(c[1]), "+f"(c[2]), "+f"(c[3])
                 : "r"(a[0]), "r"(a[1]), "r"(a[2]), "r"(a[3]), "r"(b0), "r"(b1));
}
__device__ __forceinline__ float sigmoidf_(float x) { return 1.f / (1.f + __expf(-x)); }
__device__ __forceinline__ float tanhf_(float x)    { return 2.f / (1.f + __expf(-2.f * x)) - 1.f; }

// ---------------- conversion kernels ----------------
__global__ void __launch_bounds__(256) convert_A_kernel(const float* __restrict__ x,
                                                        const float* __restrict__ h) {
    int idx = blockIdx.x * blockDim.x + threadIdx.x;
    const int TOT4 = BATCH * KDIM / 4;
    if (idx >= TOT4) return;
    int b   = idx / (KDIM / 4);
    int c4  = idx - b * (KDIM / 4);
    int col = c4 * 4;
    float4 v;
    if (col < IN_SZ) v = *(const float4*)(x + (size_t)b * IN_SZ + col);
    else             v = *(const float4*)(h + (size_t)b * HID + (col - IN_SZ));
    __half2 lo = __floats2half2_rn(v.x, v.y);
    __half2 hi = __floats2half2_rn(v.z, v.w);
    uint2 pk = make_uint2(*reinterpret_cast<uint32_t*>(&lo), *reinterpret_cast<uint32_t*>(&hi));
    *reinterpret_cast<uint2*>(g_A + (size_t)b * KDIM + col) = pk;
}

__global__ void __launch_bounds__(256) convert_W_kernel(
    const float* __restrict__ W0, const float* __restrict__ W1,
    const float* __restrict__ W2, const float* __restrict__ W3,
    const float* __restrict__ bb0, const float* __restrict__ bb1,
    const float* __restrict__ bb2, const float* __restrict__ bb3) {
    int idx = blockIdx.x * blockDim.x + threadIdx.x;
    const int TOT4 = NDIM * KDIM / 4;
    if (idx >= TOT4) return;
    int n   = idx / (KDIM / 4);
    int c4  = idx - n * (KDIM / 4);
    int col = c4 * 4;
    int g = n & 3, hh = n >> 2;
    const float* W = (g == 0) ? W0 : (g == 1) ? W1 : (g == 2) ? W2 : W3;
    float4 v = *(const float4*)(W + (size_t)hh * KDIM + col);
    __half2 lo = __floats2half2_rn(v.x, v.y);
    __half2 hi = __floats2half2_rn(v.z, v.w);
    uint2 pk = make_uint2(*reinterpret_cast<uint32_t*>(&lo), *reinterpret_cast<uint32_t*>(&hi));
    *reinterpret_cast<uint2*>(g_W + (size_t)n * KDIM + col) = pk;
    if (c4 == 0) {
        const float* bp = (g == 0) ? bb0 : (g == 1) ? bb1 : (g == 2) ? bb2 : bb3;
        g_bias[n] = bp[hh];
    }
}

// ---------------- fused GEMM + LSTM kernel (mma.sync HMMA path) ----------------
// 128 threads = 4 warps, warp grid 2(M) x 2(N), warp tile 64x64.
__global__ void __launch_bounds__(128, 2) lstm_gemm_kernel(const float* __restrict__ c_prev,
                                                           float* __restrict__ out) {
    extern __shared__ char smem[];
    const uint32_t sbase = smem_u32(smem);
    float* bias_sm = reinterpret_cast<float*>(smem);             // 512 B
    float* EP      = reinterpret_cast<float*>(smem + SMEM_CTRL); // epilogue staging, 64 KB

    const int tid  = threadIdx.x;
    const int wid  = tid >> 5;
    const int lane = tid & 31;
    const int warp_m = wid & 1;     // 0..1 -> 64-row slice
    const int warp_n = wid >> 1;    // 0..1 -> 64-col slice
    const int m0 = blockIdx.y * BM;
    const int n0 = blockIdx.x * BN;

    bias_sm[tid] = g_bias[n0 + tid];   // 128 threads, BN=128

    const __half* __restrict__ Ab = g_A + (size_t)m0 * KDIM;
    const __half* __restrict__ Wb = g_W + (size_t)n0 * KDIM;

    // per-thread cp.async mapping: 1024 16B chunks per tile, 128 threads -> 8 each
    auto load_stage = [&](int s, int kt) {
        const uint32_t a_s = sbase + SMEM_CTRL + s * STAGE_BYTES;
        const uint32_t b_s = a_s + A_TILE;
        const __half* asrc = Ab + kt * BK;
        const __half* bsrc = Wb + kt * BK;
#pragma unroll
        for (int i = 0; i < 8; i++) {
            int idx = i * 128 + tid;
            int r = idx >> 3, c16 = idx & 7;
            cp_async16(a_s + swz128(r * 128 + c16 * 16), asrc + (size_t)r * KDIM + c16 * 8);
        }
#pragma unroll
        for (int i = 0; i < 8; i++) {
            int idx = i * 128 + tid;
            int r = idx >> 3, c16 = idx & 7;
            cp_async16(b_s + swz128(r * 128 + c16 * 16), bsrc + (size_t)r * KDIM + c16 * 8);
        }
        cp_commit();
    };

    float acc[4][8][4];
#pragma unroll
    for (int mt = 0; mt < 4; mt++)
#pragma unroll
        for (int nt = 0; nt < 8; nt++)
#pragma unroll
            for (int q = 0; q < 4; q++) acc[mt][nt][q] = 0.f;

    const int lrow  = lane & 15;           // row within 16-row ldmatrix tile
    const int lkoff = (lane >> 4) * 16;    // byte offset: second 8 k-columns

    load_stage(0, 0);
    load_stage(1, 1);
    int load_k = 2;

    for (int k = 0; k < KITERS; k++) {
        const int s = k % STAGES;
        cp_wait<STAGES - 2>();
        __syncthreads();
        if (load_k < KITERS) { load_stage(load_k % STAGES, load_k); load_k++; }

        const uint32_t a_s = sbase + SMEM_CTRL + s * STAGE_BYTES;
        const uint32_t b_s = a_s + A_TILE;
#pragma unroll
        for (int ks = 0; ks < 4; ks++) {
            uint32_t af[4][4];
#pragma unroll
            for (int mt = 0; mt < 4; mt++) {
                uint32_t addr = a_s + swz128((warp_m * 64 + mt * 16 + lrow) * 128 + ks * 32 + lkoff);
                ldsm4(af[mt], addr);
            }
            uint32_t bf[4][4];
#pragma unroll
            for (int nt2 = 0; nt2 < 4; nt2++) {
                uint32_t addr = b_s + swz128((warp_n * 64 + nt2 * 16 + lrow) * 128 + ks * 32 + lkoff);
                ldsm4(bf[nt2], addr);
            }
#pragma unroll
            for (int mt = 0; mt < 4; mt++)
#pragma unroll
                for (int nt = 0; nt < 8; nt++)
                    mma16816(acc[mt][nt], af[mt], bf[nt >> 1][nt & 1], bf[nt >> 1][2 + (nt & 1)]);
        }
    }

    // -------- epilogue: stage accum to SMEM, then fused LSTM pointwise --------
    __syncthreads();   // all reads of stage SMEM done; EP overlays stage area

    const int g4 = lane >> 2;        // row group 0..7
    const int t4 = lane & 3;         // col pair 0..3
#pragma unroll
    for (int mt = 0; mt < 4; mt++) {
#pragma unroll
        for (int nt = 0; nt < 8; nt++) {
            int row = warp_m * 64 + mt * 16 + g4;
            int col = warp_n * 64 + nt * 8 + 2 * t4;
            *reinterpret_cast<float2*>(&EP[row * BN + col]) =
                make_float2(acc[mt][nt][0], acc[mt][nt][1]);
            *reinterpret_cast<float2*>(&EP[(row + 8) * BN + col]) =
                make_float2(acc[mt][nt][2], acc[mt][nt][3]);
        }
    }
    __syncthreads();

    const int h0 = n0 >> 2;                       // 32 hidden units per CTA
    float* h_out = out;
    float* c_out = out + (size_t)BATCH * HID;
#pragma unroll
    for (int it = 0; it < (BM * (BN / 4)) / 128; it++) {
        int cell = it * 128 + tid;
        int ml = cell >> 5;                       // 0..127
        int hl = cell & 31;                       // 0..31
        float4 gv = *reinterpret_cast<float4*>(&EP[ml * BN + 4 * hl]);
        float4 bv = *reinterpret_cast<float4*>(&bias_sm[4 * hl]);
        float it_g = sigmoidf_(gv.x + bv.x);
        float ft   = sigmoidf_(gv.y + bv.y);
        float gt   = tanhf_(gv.z + bv.z);
        float ot   = sigmoidf_(gv.w + bv.w);
        int m = m0 + ml;
        int h = h0 + hl;
        float ct = ft * c_prev[(size_t)m * HID + h] + it_g * gt;
        h_out[(size_t)m * HID + h] = ot * tanhf_(ct);
        c_out[(size_t)m * HID + h] = ct;
    }
}

// ---------------- launch ----------------
extern "C" void kernel_launch(void* const* d_in, const int* in_sizes, int n_in,
                              void* d_out, int out_size) {
    const float* x_t    = (const float*)d_in[0];
    const float* h_prev = (const float*)d_in[1];
    const float* c_prev = (const float*)d_in[2];
    const float* W_i = (const float*)d_in[3];
    const float* b_i = (const float*)d_in[4];
    const float* W_f = (const float*)d_in[5];
    const float* b_f = (const float*)d_in[6];
    const float* W_c = (const float*)d_in[7];
    const float* b_c = (const float*)d_in[8];
    const float* W_o = (const float*)d_in[9];
    const float* b_o = (const float*)d_in[10];
    float* out = (float*)d_out;

    cudaFuncSetAttribute(lstm_gemm_kernel,
                         cudaFuncAttributeMaxDynamicSharedMemorySize, SMEM_TOTAL);

    convert_A_kernel<<<(BATCH * KDIM / 4 + 255) / 256, 256>>>(x_t, h_prev);
    convert_W_kernel<<<(NDIM * KDIM / 4 + 255) / 256, 256>>>(W_i, W_f, W_c, W_o,
                                                             b_i, b_f, b_c, b_o);
    dim3 grid(NDIM / BN, BATCH / BM);  // 64 x 32
    lstm_gemm_kernel<<<grid, 128, SMEM_TOTAL>>>(c_prev, out);
}

// round 5
// speedup vs baseline: 1.1336x; 1.1336x over previous
#include <cuda_runtime.h>
#include <cuda_fp16.h>
#include <cstdint>

// ---------------- problem constants ----------------
static constexpr int BATCH = 4096;
static constexpr int IN_SZ = 1024;
static constexpr int HID   = 2048;
static constexpr int KDIM  = 3072;   // IN_SZ + HID
static constexpr int NDIM  = 8192;   // 4*HID, gate-interleaved rows: n = 4*h + gate

// ---------------- GEMM tiling ----------------
static constexpr int BM = 128;
static constexpr int BN = 128;
static constexpr int BK = 64;
static constexpr int KITERS = KDIM / BK;     // 48
static constexpr int STAGES = 3;
static constexpr int A_TILE = BM * BK * 2;   // 16 KB
static constexpr int B_TILE = BN * BK * 2;   // 16 KB
static constexpr int STAGE_BYTES = A_TILE + B_TILE;   // 32 KB
static constexpr int SMEM_CTRL = 1024;
static constexpr int SMEM_TOTAL = SMEM_CTRL + STAGES * STAGE_BYTES;  // 99328

// ---------------- device scratch (no allocs allowed) ----------------
__device__ __half g_A[(size_t)BATCH * KDIM];   // fp16 [x_t | h_prev], 25 MB
__device__ __half g_W[(size_t)NDIM * KDIM];    // fp16 gate-interleaved, 50 MB
__device__ float  g_bias[NDIM];

// ---------------- helpers ----------------
__device__ __forceinline__ uint32_t smem_u32(const void* p) {
    uint32_t a;
    asm("{ .reg .u64 t; cvta.to.shared.u64 t, %1; cvt.u32.u64 %0, t; }" : "=r"(a) : "l"(p));
    return a;
}
__device__ __forceinline__ uint32_t swz128(uint32_t off) {
    return off ^ ((off >> 3) & 0x70);
}
__device__ __forceinline__ void cp_async16(uint32_t dst, const void* src) {
    asm volatile("cp.async.cg.shared.global [%0], [%1], 16;" :: "r"(dst), "l"(src) : "memory");
}
__device__ __forceinline__ void cp_commit() {
    asm volatile("cp.async.commit_group;" ::: "memory");
}
template <int N>
__device__ __forceinline__ void cp_wait() {
    asm volatile("cp.async.wait_group %0;" :: "n"(N) : "memory");
}
__device__ __forceinline__ void ldsm4(uint32_t* r, uint32_t addr) {
    asm volatile("ldmatrix.sync.aligned.m8n8.x4.shared.b16 {%0,%1,%2,%3}, [%4];"
                 : "=r"(r[0]), "=r"(r[1]), "=r"(r[2]), "=r"(r[3]) : "r"(addr));
}
__device__ __forceinline__ void mma16816(float* c, const uint32_t* a, uint32_t b0, uint32_t b1) {
    asm volatile("mma.sync.aligned.m16n8k16.row.col.f32.f16.f16.f32 "
                 "{%0,%1,%2,%3}, {%4,%5,%6,%7}, {%8,%9}, {%0,%1,%2,%3};"
                 : "+f"(c[0]), "+f"(c[1]), "+f"(c[2]), "+f"(c[3])
                 : "r"(a[0]), "r"(a[1]), "r"(a[2]), "r"(a[3]), "r"(b0), "r"(b1));
}
__device__ __forceinline__ float sigmoidf_(float x) { return 1.f / (1.f + __expf(-x)); }
__device__ __forceinline__ float tanhf_(float x)    { return 2.f / (1.f + __expf(-2.f * x)) - 1.f; }

// ---------------- conversion kernels ----------------
__global__ void __launch_bounds__(256) convert_A_kernel(const float* __restrict__ x,
                                                        const float* __restrict__ h) {
    int idx = blockIdx.x * blockDim.x + threadIdx.x;
    const int TOT4 = BATCH * KDIM / 4;
    if (idx >= TOT4) return;
    int b   = idx / (KDIM / 4);
    int c4  = idx - b * (KDIM / 4);
    int col = c4 * 4;
    float4 v;
    if (col < IN_SZ) v = *(const float4*)(x + (size_t)b * IN_SZ + col);
    else             v = *(const float4*)(h + (size_t)b * HID + (col - IN_SZ));
    __half2 lo = __floats2half2_rn(v.x, v.y);
    __half2 hi = __floats2half2_rn(v.z, v.w);
    uint2 pk = make_uint2(*reinterpret_cast<uint32_t*>(&lo), *reinterpret_cast<uint32_t*>(&hi));
    *reinterpret_cast<uint2*>(g_A + (size_t)b * KDIM + col) = pk;
}

__global__ void __launch_bounds__(256) convert_W_kernel(
    const float* __restrict__ W0, const float* __restrict__ W1,
    const float* __restrict__ W2, const float* __restrict__ W3,
    const float* __restrict__ bb0, const float* __restrict__ bb1,
    const float* __restrict__ bb2, const float* __restrict__ bb3) {
    int idx = blockIdx.x * blockDim.x + threadIdx.x;
    const int TOT4 = NDIM * KDIM / 4;
    if (idx >= TOT4) return;
    int n   = idx / (KDIM / 4);
    int c4  = idx - n * (KDIM / 4);
    int col = c4 * 4;
    int g = n & 3, hh = n >> 2;
    const float* W = (g == 0) ? W0 : (g == 1) ? W1 : (g == 2) ? W2 : W3;
    float4 v = *(const float4*)(W + (size_t)hh * KDIM + col);
    __half2 lo = __floats2half2_rn(v.x, v.y);
    __half2 hi = __floats2half2_rn(v.z, v.w);
    uint2 pk = make_uint2(*reinterpret_cast<uint32_t*>(&lo), *reinterpret_cast<uint32_t*>(&hi));
    *reinterpret_cast<uint2*>(g_W + (size_t)n * KDIM + col) = pk;
    if (c4 == 0) {
        const float* bp = (g == 0) ? bb0 : (g == 1) ? bb1 : (g == 2) ? bb2 : bb3;
        g_bias[n] = bp[hh];
    }
}

// ---------------- fused GEMM + LSTM kernel (mma.sync HMMA path) ----------------
// 256 threads = 8 warps, warp grid 4(M) x 2(N), warp tile 32x64.
// k-step fragments double-buffered: LDSM of ks+1 overlaps MMAs of ks.
__global__ void __launch_bounds__(256, 2) lstm_gemm_kernel(const float* __restrict__ c_prev,
                                                           float* __restrict__ out) {
    extern __shared__ char smem[];
    const uint32_t sbase = smem_u32(smem);
    float* bias_sm = reinterpret_cast<float*>(smem);             // 512 B
    float* EP      = reinterpret_cast<float*>(smem + SMEM_CTRL); // epilogue staging, 64 KB

    const int tid  = threadIdx.x;
    const int wid  = tid >> 5;
    const int lane = tid & 31;
    const int warp_m = wid & 3;     // 0..3 -> 32-row slice
    const int warp_n = wid >> 2;    // 0..1 -> 64-col slice
    const int m0 = blockIdx.y * BM;
    const int n0 = blockIdx.x * BN;

    if (tid < BN) bias_sm[tid] = g_bias[n0 + tid];

    const __half* __restrict__ Ab = g_A + (size_t)m0 * KDIM;
    const __half* __restrict__ Wb = g_W + (size_t)n0 * KDIM;

    auto load_stage = [&](int s, int kt) {
        const uint32_t a_s = sbase + SMEM_CTRL + s * STAGE_BYTES;
        const uint32_t b_s = a_s + A_TILE;
        const __half* asrc = Ab + kt * BK;
        const __half* bsrc = Wb + kt * BK;
#pragma unroll
        for (int i = 0; i < 4; i++) {
            int idx = i * 256 + tid;
            int r = idx >> 3, c16 = idx & 7;
            cp_async16(a_s + swz128(r * 128 + c16 * 16), asrc + (size_t)r * KDIM + c16 * 8);
        }
#pragma unroll
        for (int i = 0; i < 4; i++) {
            int idx = i * 256 + tid;
            int r = idx >> 3, c16 = idx & 7;
            cp_async16(b_s + swz128(r * 128 + c16 * 16), bsrc + (size_t)r * KDIM + c16 * 8);
        }
        cp_commit();
    };

    float acc[2][8][4];
#pragma unroll
    for (int mt = 0; mt < 2; mt++)
#pragma unroll
        for (int nt = 0; nt < 8; nt++)
#pragma unroll
            for (int q = 0; q < 4; q++) acc[mt][nt][q] = 0.f;

    const int lrow  = lane & 15;           // row within 16-row ldmatrix tile
    const int lkoff = (lane >> 4) * 16;    // byte offset: second 8 k-columns

    // fragment double buffers
    uint32_t af[2][2][4];
    uint32_t bf[2][4][4];

    auto load_frag = [&](uint32_t a_s, uint32_t b_s, int ks, int buf) {
#pragma unroll
        for (int mt = 0; mt < 2; mt++) {
            uint32_t addr = a_s + swz128((warp_m * 32 + mt * 16 + lrow) * 128 + ks * 32 + lkoff);
            ldsm4(af[buf][mt], addr);
        }
#pragma unroll
        for (int nt2 = 0; nt2 < 4; nt2++) {
            uint32_t addr = b_s + swz128((warp_n * 64 + nt2 * 16 + lrow) * 128 + ks * 32 + lkoff);
            ldsm4(bf[buf][nt2], addr);
        }
    };

    load_stage(0, 0);
    load_stage(1, 1);
    int load_k = 2;

    for (int k = 0; k < KITERS; k++) {
        const int s = k % STAGES;
        cp_wait<STAGES - 2>();
        __syncthreads();
        if (load_k < KITERS) { load_stage(load_k % STAGES, load_k); load_k++; }

        const uint32_t a_s = sbase + SMEM_CTRL + s * STAGE_BYTES;
        const uint32_t b_s = a_s + A_TILE;

        load_frag(a_s, b_s, 0, 0);
#pragma unroll
        for (int ks = 0; ks < 4; ks++) {
            const int cur = ks & 1;
            if (ks < 3) load_frag(a_s, b_s, ks + 1, cur ^ 1);
#pragma unroll
            for (int mt = 0; mt < 2; mt++)
#pragma unroll
                for (int nt = 0; nt < 8; nt++)
                    mma16816(acc[mt][nt], af[cur][mt],
                             bf[cur][nt >> 1][nt & 1], bf[cur][nt >> 1][2 + (nt & 1)]);
        }
    }

    // -------- epilogue: stage accum to SMEM, then fused LSTM pointwise --------
    __syncthreads();   // all reads of stage SMEM done; EP overlays stage area

    const int g4 = lane >> 2;        // row group 0..7
    const int t4 = lane & 3;         // col pair 0..3
#pragma unroll
    for (int mt = 0; mt < 2; mt++) {
#pragma unroll
        for (int nt = 0; nt < 8; nt++) {
            int row = warp_m * 32 + mt * 16 + g4;
            int col = warp_n * 64 + nt * 8 + 2 * t4;
            *reinterpret_cast<float2*>(&EP[row * BN + col]) =
                make_float2(acc[mt][nt][0], acc[mt][nt][1]);
            *reinterpret_cast<float2*>(&EP[(row + 8) * BN + col]) =
                make_float2(acc[mt][nt][2], acc[mt][nt][3]);
        }
    }
    __syncthreads();

    const int h0 = n0 >> 2;                       // 32 hidden units per CTA
    float* h_out = out;
    float* c_out = out + (size_t)BATCH * HID;
#pragma unroll
    for (int it = 0; it < (BM * (BN / 4)) / 256; it++) {
        int cell = it * 256 + tid;
        int ml = cell >> 5;                       // 0..127
        int hl = cell & 31;                       // 0..31
        float4 gv = *reinterpret_cast<float4*>(&EP[ml * BN + 4 * hl]);
        float4 bv = *reinterpret_cast<float4*>(&bias_sm[4 * hl]);
        float it_g = sigmoidf_(gv.x + bv.x);
        float ft   = sigmoidf_(gv.y + bv.y);
        float gt   = tanhf_(gv.z + bv.z);
        float ot   = sigmoidf_(gv.w + bv.w);
        int m = m0 + ml;
        int h = h0 + hl;
        float ct = ft * c_prev[(size_t)m * HID + h] + it_g * gt;
        h_out[(size_t)m * HID + h] = ot * tanhf_(ct);
        c_out[(size_t)m * HID + h] = ct;
    }
}

// ---------------- launch ----------------
extern "C" void kernel_launch(void* const* d_in, const int* in_sizes, int n_in,
                              void* d_out, int out_size) {
    const float* x_t    = (const float*)d_in[0];
    const float* h_prev = (const float*)d_in[1];
    const float* c_prev = (const float*)d_in[2];
    const float* W_i = (const float*)d_in[3];
    const float* b_i = (const float*)d_in[4];
    const float* W_f = (const float*)d_in[5];
    const float* b_f = (const float*)d_in[6];
    const float* W_c = (const float*)d_in[7];
    const float* b_c = (const float*)d_in[8];
    const float* W_o = (const float*)d_in[9];
    const float* b_o = (const float*)d_in[10];
    float* out = (float*)d_out;

    cudaFuncSetAttribute(lstm_gemm_kernel,
                         cudaFuncAttributeMaxDynamicSharedMemorySize, SMEM_TOTAL);

    convert_A_kernel<<<(BATCH * KDIM / 4 + 255) / 256, 256>>>(x_t, h_prev);
    convert_W_kernel<<<(NDIM * KDIM / 4 + 255) / 256, 256>>>(W_i, W_f, W_c, W_o,
                                                             b_i, b_f, b_c, b_o);
    dim3 grid(NDIM / BN, BATCH / BM);  // 64 x 32
    lstm_gemm_kernel<<<grid, 256, SMEM_TOTAL>>>(c_prev, out);
}

// round 6
// speedup vs baseline: 1.1420x; 1.0074x over previous
#include <cuda_runtime.h>
#include <cuda_fp16.h>
#include <cstdint>

// ---------------- problem constants ----------------
static constexpr int BATCH = 4096;
static constexpr int IN_SZ = 1024;
static constexpr int HID   = 2048;
static constexpr int KDIM  = 3072;   // IN_SZ + HID
static constexpr int NDIM  = 8192;   // 4*HID, gate-interleaved rows: n = 4*h + gate

// ---------------- GEMM tiling ----------------
static constexpr int BM = 128;
static constexpr int BN = 128;
static constexpr int BK = 64;
static constexpr int KITERS = KDIM / BK;     // 48
static constexpr int STAGES = 3;
static constexpr int A_TILE = BM * BK * 2;   // 16 KB
static constexpr int B_TILE = BN * BK * 2;   // 16 KB
static constexpr int STAGE_BYTES = A_TILE + B_TILE;   // 32 KB
static constexpr int SMEM_CTRL = 1024;
static constexpr int SMEM_TOTAL = SMEM_CTRL + STAGES * STAGE_BYTES;  // 99328

// ---------------- device scratch (no allocs allowed) ----------------
__device__ __half g_A[(size_t)BATCH * KDIM];   // fp16 [x_t | h_prev], 25 MB
__device__ __half g_W[(size_t)NDIM * KDIM];    // fp16 gate-interleaved, 50 MB
__device__ float  g_bias[NDIM];

// ---------------- helpers ----------------
__device__ __forceinline__ uint32_t smem_u32(const void* p) {
    uint32_t a;
    asm("{ .reg .u64 t; cvta.to.shared.u64 t, %1; cvt.u32.u64 %0, t; }" : "=r"(a) : "l"(p));
    return a;
}
__device__ __forceinline__ uint32_t swz128(uint32_t off) {
    return off ^ ((off >> 3) & 0x70);
}
__device__ __forceinline__ void cp_async16(uint32_t dst, const void* src) {
    asm volatile("cp.async.cg.shared.global [%0], [%1], 16;" :: "r"(dst), "l"(src) : "memory");
}
__device__ __forceinline__ void cp_commit() {
    asm volatile("cp.async.commit_group;" ::: "memory");
}
template <int N>
__device__ __forceinline__ void cp_wait() {
    asm volatile("cp.async.wait_group %0;" :: "n"(N) : "memory");
}
__device__ __forceinline__ void ldsm4(uint32_t* r, uint32_t addr) {
    asm volatile("ldmatrix.sync.aligned.m8n8.x4.shared.b16 {%0,%1,%2,%3}, [%4];"
                 : "=r"(r[0]), "=r"(r[1]), "=r"(r[2]), "=r"(r[3]) : "r"(addr));
}
__device__ __forceinline__ void mma16816(float* c, const uint32_t* a, uint32_t b0, uint32_t b1) {
    asm volatile("mma.sync.aligned.m16n8k16.row.col.f32.f16.f16.f32 "
                 "{%0,%1,%2,%3}, {%4,%5,%6,%7}, {%8,%9}, {%0,%1,%2,%3};"
                 : "+f"(c[0]), "+f"(c[1]), "+f"(c[2]), "+f"(c[3])
                 : "r"(a[0]), "r"(a[1]), "r"(a[2]), "r"(a[3]), "r"(b0), "r"(b1));
}
__device__ __forceinline__ float sigmoidf_(float x) { return 1.f / (1.f + __expf(-x)); }
__device__ __forceinline__ float tanhf_(float x)    { return 2.f / (1.f + __expf(-2.f * x)) - 1.f; }

// ---------------- merged conversion kernel ----------------
// One grid covers: A chunks (x_t|h_prev -> g_A fp16), W chunks (4x W_g -> g_W
// gate-interleaved fp16), and bias. Unified so the independent memory streams
// overlap instead of running as serial launches.
static constexpr int A_CHUNKS = BATCH * KDIM / 4;   // 3.1M float4 chunks
static constexpr int W_CHUNKS = NDIM * KDIM / 4;    // 6.3M
static constexpr int TOT_CHUNKS = A_CHUNKS + W_CHUNKS;

__global__ void __launch_bounds__(256) convert_all_kernel(
    const float* __restrict__ x, const float* __restrict__ h,
    const float* __restrict__ W0, const float* __restrict__ W1,
    const float* __restrict__ W2, const float* __restrict__ W3,
    const float* __restrict__ bb0, const float* __restrict__ bb1,
    const float* __restrict__ bb2, const float* __restrict__ bb3) {
    int idx = blockIdx.x * blockDim.x + threadIdx.x;
    if (idx >= TOT_CHUNKS) return;
    if (idx < A_CHUNKS) {
        int b   = idx / (KDIM / 4);
        int col = (idx - b * (KDIM / 4)) * 4;
        float4 v;
        if (col < IN_SZ) v = *(const float4*)(x + (size_t)b * IN_SZ + col);
        else             v = *(const float4*)(h + (size_t)b * HID + (col - IN_SZ));
        __half2 lo = __floats2half2_rn(v.x, v.y);
        __half2 hi = __floats2half2_rn(v.z, v.w);
        uint2 pk = make_uint2(*reinterpret_cast<uint32_t*>(&lo), *reinterpret_cast<uint32_t*>(&hi));
        *reinterpret_cast<uint2*>(g_A + (size_t)b * KDIM + col) = pk;
    } else {
        int widx = idx - A_CHUNKS;
        int n   = widx / (KDIM / 4);
        int c4  = widx - n * (KDIM / 4);
        int col = c4 * 4;
        int g = n & 3, hh = n >> 2;
        const float* W = (g == 0) ? W0 : (g == 1) ? W1 : (g == 2) ? W2 : W3;
        float4 v = *(const float4*)(W + (size_t)hh * KDIM + col);
        __half2 lo = __floats2half2_rn(v.x, v.y);
        __half2 hi = __floats2half2_rn(v.z, v.w);
        uint2 pk = make_uint2(*reinterpret_cast<uint32_t*>(&lo), *reinterpret_cast<uint32_t*>(&hi));
        *reinterpret_cast<uint2*>(g_W + (size_t)n * KDIM + col) = pk;
        if (c4 == 0) {
            const float* bp = (g == 0) ? bb0 : (g == 1) ? bb1 : (g == 2) ? bb2 : bb3;
            g_bias[n] = bp[hh];
        }
    }
}

// ---------------- fused GEMM + LSTM kernel (mma.sync HMMA path) ----------------
// 256 threads = 8 warps, warp grid 4(M) x 2(N), warp tile 32x64.  (R2 core)
__global__ void __launch_bounds__(256, 2) lstm_gemm_kernel(const float* __restrict__ c_prev,
                                                           float* __restrict__ out) {
    extern __shared__ char smem[];
    const uint32_t sbase = smem_u32(smem);
    float* bias_sm = reinterpret_cast<float*>(smem);             // 512 B
    float* EP      = reinterpret_cast<float*>(smem + SMEM_CTRL); // epilogue staging, 64 KB

    const int tid  = threadIdx.x;
    const int wid  = tid >> 5;
    const int lane = tid & 31;
    const int warp_m = wid & 3;     // 0..3 -> 32-row slice
    const int warp_n = wid >> 2;    // 0..1 -> 64-col slice
    const int m0 = blockIdx.y * BM;
    const int n0 = blockIdx.x * BN;

    if (tid < BN) bias_sm[tid] = g_bias[n0 + tid];

    const __half* __restrict__ Ab = g_A + (size_t)m0 * KDIM;
    const __half* __restrict__ Wb = g_W + (size_t)n0 * KDIM;

    auto load_stage = [&](int s, int kt) {
        const uint32_t a_s = sbase + SMEM_CTRL + s * STAGE_BYTES;
        const uint32_t b_s = a_s + A_TILE;
        const __half* asrc = Ab + kt * BK;
        const __half* bsrc = Wb + kt * BK;
#pragma unroll
        for (int i = 0; i < 4; i++) {
            int idx = i * 256 + tid;
            int r = idx >> 3, c16 = idx & 7;
            cp_async16(a_s + swz128(r * 128 + c16 * 16), asrc + (size_t)r * KDIM + c16 * 8);
        }
#pragma unroll
        for (int i = 0; i < 4; i++) {
            int idx = i * 256 + tid;
            int r = idx >> 3, c16 = idx & 7;
            cp_async16(b_s + swz128(r * 128 + c16 * 16), bsrc + (size_t)r * KDIM + c16 * 8);
        }
        cp_commit();
    };

    float acc[2][8][4];
#pragma unroll
    for (int mt = 0; mt < 2; mt++)
#pragma unroll
        for (int nt = 0; nt < 8; nt++)
#pragma unroll
            for (int q = 0; q < 4; q++) acc[mt][nt][q] = 0.f;

    const int lrow  = lane & 15;           // row within 16-row ldmatrix tile
    const int lkoff = (lane >> 4) * 16;    // byte offset: second 8 k-columns

    load_stage(0, 0);
    load_stage(1, 1);
    int load_k = 2;

    for (int k = 0; k < KITERS; k++) {
        const int s = k % STAGES;
        cp_wait<STAGES - 2>();
        __syncthreads();
        if (load_k < KITERS) { load_stage(load_k % STAGES, load_k); load_k++; }

        const uint32_t a_s = sbase + SMEM_CTRL + s * STAGE_BYTES;
        const uint32_t b_s = a_s + A_TILE;
#pragma unroll
        for (int ks = 0; ks < 4; ks++) {
            uint32_t af[2][4];
#pragma unroll
            for (int mt = 0; mt < 2; mt++) {
                uint32_t addr = a_s + swz128((warp_m * 32 + mt * 16 + lrow) * 128 + ks * 32 + lkoff);
                ldsm4(af[mt], addr);
            }
            uint32_t bf[4][4];
#pragma unroll
            for (int nt2 = 0; nt2 < 4; nt2++) {
                uint32_t addr = b_s + swz128((warp_n * 64 + nt2 * 16 + lrow) * 128 + ks * 32 + lkoff);
                ldsm4(bf[nt2], addr);
            }
#pragma unroll
            for (int mt = 0; mt < 2; mt++)
#pragma unroll
                for (int nt = 0; nt < 8; nt++)
                    mma16816(acc[mt][nt], af[mt], bf[nt >> 1][nt & 1], bf[nt >> 1][2 + (nt & 1)]);
        }
    }

    // -------- epilogue: stage accum to SMEM, then fused LSTM pointwise --------
    __syncthreads();   // all reads of stage SMEM done; EP overlays stage area

    const int g4 = lane >> 2;        // row group 0..7
    const int t4 = lane & 3;         // col pair 0..3
#pragma unroll
    for (int mt = 0; mt < 2; mt++) {
#pragma unroll
        for (int nt = 0; nt < 8; nt++) {
            int row = warp_m * 32 + mt * 16 + g4;
            int col = warp_n * 64 + nt * 8 + 2 * t4;
            *reinterpret_cast<float2*>(&EP[row * BN + col]) =
                make_float2(acc[mt][nt][0], acc[mt][nt][1]);
            *reinterpret_cast<float2*>(&EP[(row + 8) * BN + col]) =
                make_float2(acc[mt][nt][2], acc[mt][nt][3]);
        }
    }
    __syncthreads();

    const int h0 = n0 >> 2;                       // 32 hidden units per CTA
    float* h_out = out;
    float* c_out = out + (size_t)BATCH * HID;
#pragma unroll
    for (int it = 0; it < (BM * (BN / 4)) / 256; it++) {
        int cell = it * 256 + tid;
        int ml = cell >> 5;                       // 0..127
        int hl = cell & 31;                       // 0..31
        float4 gv = *reinterpret_cast<float4*>(&EP[ml * BN + 4 * hl]);
        float4 bv = *reinterpret_cast<float4*>(&bias_sm[4 * hl]);
        float it_g = sigmoidf_(gv.x + bv.x);
        float ft   = sigmoidf_(gv.y + bv.y);
        float gt   = tanhf_(gv.z + bv.z);
        float ot   = sigmoidf_(gv.w + bv.w);
        int m = m0 + ml;
        int h = h0 + hl;
        float ct = ft * c_prev[(size_t)m * HID + h] + it_g * gt;
        h_out[(size_t)m * HID + h] = ot * tanhf_(ct);
        c_out[(size_t)m * HID + h] = ct;
    }
}

// ---------------- launch ----------------
extern "C" void kernel_launch(void* const* d_in, const int* in_sizes, int n_in,
                              void* d_out, int out_size) {
    const float* x_t    = (const float*)d_in[0];
    const float* h_prev = (const float*)d_in[1];
    const float* c_prev = (const float*)d_in[2];
    const float* W_i = (const float*)d_in[3];
    const float* b_i = (const float*)d_in[4];
    const float* W_f = (const float*)d_in[5];
    const float* b_f = (const float*)d_in[6];
    const float* W_c = (const float*)d_in[7];
    const float* b_c = (const float*)d_in[8];
    const float* W_o = (const float*)d_in[9];
    const float* b_o = (const float*)d_in[10];
    float* out = (float*)d_out;

    cudaFuncSetAttribute(lstm_gemm_kernel,
                         cudaFuncAttributeMaxDynamicSharedMemorySize, SMEM_TOTAL);

    convert_all_kernel<<<(TOT_CHUNKS + 255) / 256, 256>>>(
        x_t, h_prev, W_i, W_f, W_c, W_o, b_i, b_f, b_c, b_o);
    dim3 grid(NDIM / BN, BATCH / BM);  // 64 x 32
    lstm_gemm_kernel<<<grid, 256, SMEM_TOTAL>>>(c_prev, out);
}